// round 12
// baseline (speedup 1.0000x reference)
#include <cuda_runtime.h>

// DynamicMaskHead fused kernel for GB300 (sm_103a), round 12.
// Model update: L1 73% = smem CROSSBAR BYTES from weight broadcasts
// (~676 B/px at 2px/thread). Fix: 4px x 2heads per thread halves weight
// bytes/px. R9 tried this and lost to wave-fill + warp count; those are
// fixed here: NT=160 @ 4 CTA/SM (20 warps, 102-reg cap), 16-row slabs ->
// 1200 blocks ~ 2 waves. Keeps R11's {bias,w2} packing + vector phase 2.

#define WW   160
#define OW   320
#define HW   15360
#define NP   169
#define NT   160

// weight-pair layout (u64 indices in swp):
//   [0,80)    l0wT: input-major, i*8 + c
//   [80,88)   l0b
//   [88,168)  l1 blocks: c*10 + {0..7: w, 8: bias, 9: w2(pre-scaled 0.5)}
//   [168]     l2b (pre-scaled 0.5)
#define SWPAIRS 169
#define TILE_PAIRS (17 * WW)                 // 17 rows max per slab (even count)
#define SMEM_BYTES ((TILE_PAIRS + SWPAIRS + 1) * 8)

typedef unsigned long long u64;

__device__ __forceinline__ u64 pk(float lo, float hi) {
    u64 r; asm("mov.b64 %0, {%1, %2};" : "=l"(r) : "f"(lo), "f"(hi)); return r;
}
__device__ __forceinline__ u64 dup(float v) {
    u64 r; asm("mov.b64 %0, {%1, %1};" : "=l"(r) : "f"(v)); return r;
}
__device__ __forceinline__ void upk(u64 v, float& lo, float& hi) {
    asm("mov.b64 {%0, %1}, %2;" : "=f"(lo), "=f"(hi) : "l"(v));
}
__device__ __forceinline__ u64 ffma2(u64 a, u64 b, u64 c) {
    u64 d; asm("fma.rn.f32x2 %0, %1, %2, %3;" : "=l"(d) : "l"(a), "l"(b), "l"(c)); return d;
}
__device__ __forceinline__ u64 add2(u64 a, u64 b) {
    u64 d; asm("add.rn.f32x2 %0, %1, %2;" : "=l"(d) : "l"(a), "l"(b)); return d;
}
__device__ __forceinline__ u64 mul2(u64 a, u64 b) {
    u64 d; asm("mul.rn.f32x2 %0, %1, %2;" : "=l"(d) : "l"(a), "l"(b)); return d;
}
__device__ __forceinline__ u64 relu2(u64 v) {
    float lo, hi; upk(v, lo, hi);
    return pk(fmaxf(lo, 0.0f), fmaxf(hi, 0.0f));
}
// x = 0.5*logit: sigmoid(L) = 0.5*tanh(0.5L) + 0.5
__device__ __forceinline__ float sig_h(float x) {
    float t;
    asm("tanh.approx.f32 %0, %1;" : "=f"(t) : "f"(x));
    return fmaf(0.5f, t, 0.5f);
}

__global__ __launch_bounds__(NT, 4)
void dmh_kernel(const float* __restrict__ feats,     // [2, 8, 96, 160]
                const float* __restrict__ p1,        // [N, 169]
                const float* __restrict__ p2,        // [N, 169]
                const float* __restrict__ loc,       // [N, 2]
                const float* __restrict__ off,       // [N, 2]
                const int*   __restrict__ imi,       // [N]
                const int*   __restrict__ fpn,       // [N]
                float*       __restrict__ out)       // [2, N, 192, 320]
{
    extern __shared__ u64 smem_u64[];
    u64* sLp = smem_u64;                       // [TILE_PAIRS] packed half-logits
    u64* swp = smem_u64 + TILE_PAIRS;          // [SWPAIRS] weight pairs

    const int tid    = threadIdx.x;
    const int inst   = blockIdx.x;
    const int slab   = blockIdx.y;             // 0..5
    const int n_inst = gridDim.x;

    // ---- Repack: interleave head0/head1 weights into pairs (NT < NP: loop) --
    for (int t = tid; t < NP; t += NT) {
        float w1 = p1[inst * NP + t];
        float w2 = p2[inst * NP + t];
        int d;
        if      (t < 80)  { const int c = t / 10; d = (t - c * 10) * 8 + c; }        // l0wT
        else if (t < 144) { const int i = t - 80; d = 88 + (i / 8) * 10 + (i % 8); } // l1w
        else if (t < 152) { d = 88 + (t - 144) * 10 + 9; w1 *= 0.5f; w2 *= 0.5f; }   // l2w
        else if (t < 160) { d = 80 + (t - 152); }                                    // l0b
        else if (t < 168) { d = 88 + (t - 160) * 10 + 8; }                           // l1b
        else              { d = 168; w1 *= 0.5f; w2 *= 0.5f; }                       // l2b
        swp[d] = pk(w1, w2);
    }

    const int   lvl     = fpn[inst];
    const float inv_soi = 1.0f / (64.0f * (float)(1 << lvl));
    const float lx0 = loc[2 * inst + 0];
    const float ly0 = loc[2 * inst + 1];
    const float lx1 = lx0 + off[2 * inst + 0] * 128.0f;
    const float ly1 = ly0 + off[2 * inst + 1] * 128.0f;
    const float* fb = feats + (size_t)imi[inst] * (8 * HW);
    const float dxs = -8.0f * inv_soi;
    __syncthreads();

    // ---------------- Phase 1: packed MLP, 4 px x 2 heads per iter ----------
    // slab s -> output rows [32s, 32s+32) -> input rows [16s-(s>0), 16s+16)
    const int ybase = 16 * slab - (slab ? 1 : 0);
    const int nrows = 16 + (slab ? 1 : 0);     // 16 or 17
    const int ng    = nrows * (WW / 4);        // 4-px groups: 640 or 680

    #pragma unroll 1
    for (int g = tid; g < ng; g += NT) {
        const int rowl = g / (WW / 4);
        const int px   = (g - rowl * (WW / 4)) * 4;
        const int y    = ybase + rowl;
        const int base = y * WW + px;

        // coordinate pairs {head0, head1} for the 4 pixels
        const float yc = (float)(y * 8 + 4);
        const float xc = (float)(px * 8 + 4);
        const u64 yp = pk((ly0 - yc) * inv_soi, (ly1 - yc) * inv_soi);
        const u64 xp0 = pk((lx0 - xc) * inv_soi, (lx1 - xc) * inv_soi);
        const u64 dd  = dup(dxs);
        const u64 xp1 = add2(xp0, dd);
        const u64 xp2 = add2(xp1, dd);
        const u64 xp3 = add2(xp2, dd);

        // layer-0 accumulators: 4 px x 8 ch packed pairs (bias init)
        u64 a[4][8];
        {
            const ulonglong2* bp = reinterpret_cast<const ulonglong2*>(swp + 80);
            const ulonglong2 b0 = bp[0], b1 = bp[1], b2 = bp[2], b3 = bp[3];
            #pragma unroll
            for (int k = 0; k < 4; ++k) {
                a[k][0] = b0.x; a[k][1] = b0.y; a[k][2] = b1.x; a[k][3] = b1.y;
                a[k][4] = b2.x; a[k][5] = b2.y; a[k][6] = b3.x; a[k][7] = b3.y;
            }
        }

        #define L0STEP(I, X0, X1, X2, X3)                                     \
        {                                                                     \
            const ulonglong2* Wp = reinterpret_cast<const ulonglong2*>(swp + (I) * 8); \
            const ulonglong2 wa = Wp[0], wb = Wp[1], wc = Wp[2], wd = Wp[3];  \
            a[0][0] = ffma2(X0, wa.x, a[0][0]); a[1][0] = ffma2(X1, wa.x, a[1][0]); \
            a[2][0] = ffma2(X2, wa.x, a[2][0]); a[3][0] = ffma2(X3, wa.x, a[3][0]); \
            a[0][1] = ffma2(X0, wa.y, a[0][1]); a[1][1] = ffma2(X1, wa.y, a[1][1]); \
            a[2][1] = ffma2(X2, wa.y, a[2][1]); a[3][1] = ffma2(X3, wa.y, a[3][1]); \
            a[0][2] = ffma2(X0, wb.x, a[0][2]); a[1][2] = ffma2(X1, wb.x, a[1][2]); \
            a[2][2] = ffma2(X2, wb.x, a[2][2]); a[3][2] = ffma2(X3, wb.x, a[3][2]); \
            a[0][3] = ffma2(X0, wb.y, a[0][3]); a[1][3] = ffma2(X1, wb.y, a[1][3]); \
            a[2][3] = ffma2(X2, wb.y, a[2][3]); a[3][3] = ffma2(X3, wb.y, a[3][3]); \
            a[0][4] = ffma2(X0, wc.x, a[0][4]); a[1][4] = ffma2(X1, wc.x, a[1][4]); \
            a[2][4] = ffma2(X2, wc.x, a[2][4]); a[3][4] = ffma2(X3, wc.x, a[3][4]); \
            a[0][5] = ffma2(X0, wc.y, a[0][5]); a[1][5] = ffma2(X1, wc.y, a[1][5]); \
            a[2][5] = ffma2(X2, wc.y, a[2][5]); a[3][5] = ffma2(X3, wc.y, a[3][5]); \
            a[0][6] = ffma2(X0, wd.x, a[0][6]); a[1][6] = ffma2(X1, wd.x, a[1][6]); \
            a[2][6] = ffma2(X2, wd.x, a[2][6]); a[3][6] = ffma2(X3, wd.x, a[3][6]); \
            a[0][7] = ffma2(X0, wd.y, a[0][7]); a[1][7] = ffma2(X1, wd.y, a[1][7]); \
            a[2][7] = ffma2(X2, wd.y, a[2][7]); a[3][7] = ffma2(X3, wd.y, a[3][7]); \
        }

        L0STEP(0, xp0, xp1, xp2, xp3)
        L0STEP(1, yp,  yp,  yp,  yp)

        // features in two half-groups of 4 channels (bounds live regs)
        #pragma unroll
        for (int h = 0; h < 2; ++h) {
            float4 f0 = *reinterpret_cast<const float4*>(fb + (4 * h + 0) * HW + base);
            float4 f1 = *reinterpret_cast<const float4*>(fb + (4 * h + 1) * HW + base);
            float4 f2 = *reinterpret_cast<const float4*>(fb + (4 * h + 2) * HW + base);
            float4 f3 = *reinterpret_cast<const float4*>(fb + (4 * h + 3) * HW + base);
            #define FEED(J, F)                                                \
            {                                                                 \
                const u64 d0 = dup(F.x), d1 = dup(F.y);                       \
                const u64 d2 = dup(F.z), d3 = dup(F.w);                       \
                L0STEP(2 + 4 * h + (J), d0, d1, d2, d3)                       \
            }
            FEED(0, f0) FEED(1, f1) FEED(2, f2) FEED(3, f3)
            #undef FEED
        }
        #undef L0STEP

        #pragma unroll
        for (int k = 0; k < 4; ++k)
            #pragma unroll
            for (int c = 0; c < 8; ++c)
                a[k][c] = relu2(a[k][c]);

        // layer 1 channel-outer ({bias,w2} packed), layer 2 streamed into o[4]
        u64 o[4];
        { const u64 b2 = swp[168]; o[0] = b2; o[1] = b2; o[2] = b2; o[3] = b2; }
        #pragma unroll
        for (int c = 0; c < 8; ++c) {
            const ulonglong2* Wp = reinterpret_cast<const ulonglong2*>(swp + 88 + c * 10);
            const ulonglong2 wa = Wp[0], wb = Wp[1], wc = Wp[2], wd = Wp[3];
            const ulonglong2 bw = Wp[4];          // {bias, w2}
            u64 t0 = ffma2(a[0][0], wa.x, bw.x);
            u64 t1 = ffma2(a[1][0], wa.x, bw.x);
            u64 t2 = ffma2(a[2][0], wa.x, bw.x);
            u64 t3 = ffma2(a[3][0], wa.x, bw.x);
            t0 = ffma2(a[0][1], wa.y, t0); t1 = ffma2(a[1][1], wa.y, t1);
            t2 = ffma2(a[2][1], wa.y, t2); t3 = ffma2(a[3][1], wa.y, t3);
            t0 = ffma2(a[0][2], wb.x, t0); t1 = ffma2(a[1][2], wb.x, t1);
            t2 = ffma2(a[2][2], wb.x, t2); t3 = ffma2(a[3][2], wb.x, t3);
            t0 = ffma2(a[0][3], wb.y, t0); t1 = ffma2(a[1][3], wb.y, t1);
            t2 = ffma2(a[2][3], wb.y, t2); t3 = ffma2(a[3][3], wb.y, t3);
            t0 = ffma2(a[0][4], wc.x, t0); t1 = ffma2(a[1][4], wc.x, t1);
            t2 = ffma2(a[2][4], wc.x, t2); t3 = ffma2(a[3][4], wc.x, t3);
            t0 = ffma2(a[0][5], wc.y, t0); t1 = ffma2(a[1][5], wc.y, t1);
            t2 = ffma2(a[2][5], wc.y, t2); t3 = ffma2(a[3][5], wc.y, t3);
            t0 = ffma2(a[0][6], wd.x, t0); t1 = ffma2(a[1][6], wd.x, t1);
            t2 = ffma2(a[2][6], wd.x, t2); t3 = ffma2(a[3][6], wd.x, t3);
            t0 = ffma2(a[0][7], wd.y, t0); t1 = ffma2(a[1][7], wd.y, t1);
            t2 = ffma2(a[2][7], wd.y, t2); t3 = ffma2(a[3][7], wd.y, t3);
            o[0] = ffma2(relu2(t0), bw.y, o[0]);
            o[1] = ffma2(relu2(t1), bw.y, o[1]);
            o[2] = ffma2(relu2(t2), bw.y, o[2]);
            o[3] = ffma2(relu2(t3), bw.y, o[3]);
        }

        // packed half-logit pairs, 2 x STS.128
        u64* dst = sLp + rowl * WW + px;
        *reinterpret_cast<ulonglong2*>(dst)     = make_ulonglong2(o[0], o[1]);
        *reinterpret_cast<ulonglong2*>(dst + 2) = make_ulonglong2(o[2], o[3]);
    }
    __syncthreads();

    // ---------------- Phase 2: packed bilinear x2 + sigmoid ------------------
    // S_i = P[rA][i] + P[rB][i]  (rA==rB for odd rows -> S = 2P)
    //   col 4g: 0.25*(S_{cm1}+S_{c0})   4g+1: 0.5*S_{c0}
    //   4g+2:   0.25*(S_{c0}+S_{c1})    4g+3: 0.5*S_{c1}
    const u64 H = dup(0.5f);
    const u64 Q = dup(0.25f);
    float* ob0 = out + (size_t)inst * (192 * OW);
    float* ob1 = out + ((size_t)n_inst + inst) * (192 * OW);

    // 32 output rows x 80 quad-groups = 2560 items = exactly 16 iters at NT=160
    #pragma unroll 1
    for (int it = 0; it < 16; ++it) {
        const int q   = tid + it * NT;
        const int oyl = q / 80;                 // 0..31
        const int g   = q - oyl * 80;           // 0..79
        const int oy  = 32 * slab + oyl;

        const int r1  = oy >> 1;
        const int rA  = (oy & 1) ? r1 : ((r1 > 0) ? r1 - 1 : 0);
        const u64* RB = sLp + (r1 - ybase) * WW;
        const u64* RA = sLp + (rA - ybase) * WW;

        const int c0  = 2 * g;                  // even -> 16B aligned
        const int cm1 = (g > 0) ? c0 - 1 : c0;

        const ulonglong2 pb = *reinterpret_cast<const ulonglong2*>(RB + c0);
        const ulonglong2 pa = *reinterpret_cast<const ulonglong2*>(RA + c0);
        const u64 Sm = add2(RA[cm1], RB[cm1]);
        const u64 S0 = add2(pa.x, pb.x);
        const u64 S1 = add2(pa.y, pb.y);

        const u64 e0 = mul2(add2(Sm, S0), Q);
        const u64 e1 = mul2(S0, H);
        const u64 e2 = mul2(add2(S0, S1), Q);
        const u64 e3 = mul2(S1, H);

        float a0, b0, a1, b1, a2, b2, a3, b3;
        upk(e0, a0, b0); upk(e1, a1, b1); upk(e2, a2, b2); upk(e3, a3, b3);

        float4 v0, v1;
        v0.x = sig_h(a0); v0.y = sig_h(a1); v0.z = sig_h(a2); v0.w = sig_h(a3);
        v1.x = sig_h(b0); v1.y = sig_h(b1); v1.z = sig_h(b2); v1.w = sig_h(b3);

        const int o = oy * OW + 4 * g;
        *reinterpret_cast<float4*>(ob0 + o) = v0;
        *reinterpret_cast<float4*>(ob1 + o) = v1;
    }
}

extern "C" void kernel_launch(void* const* d_in, const int* in_sizes, int n_in,
                              void* d_out, int out_size)
{
    const float* feats = (const float*)d_in[0];
    const float* p1    = (const float*)d_in[1];
    const float* p2    = (const float*)d_in[2];
    const float* loc   = (const float*)d_in[3];
    const float* off   = (const float*)d_in[4];
    const int*   imi   = (const int*)  d_in[5];
    const int*   fpn   = (const int*)  d_in[6];
    float* out = (float*)d_out;

    const int n_inst = in_sizes[5];   // 200

    static bool attr_set = false;
    if (!attr_set) {
        cudaFuncSetAttribute(dmh_kernel,
                             cudaFuncAttributeMaxDynamicSharedMemorySize,
                             (int)SMEM_BYTES);
        attr_set = true;
    }

    dim3 grid(n_inst, 6);             // 1200 blocks ~ 2 waves @ 4 CTA/SM
    dmh_kernel<<<grid, NT, SMEM_BYTES>>>(feats, p1, p2, loc, off, imi, fpn, out);
}